// round 8
// baseline (speedup 1.0000x reference)
#include <cuda_runtime.h>

#define NSTATES 128

static __device__ __forceinline__ float warp_max(float v) {
#pragma unroll
    for (int d = 16; d; d >>= 1) v = fmaxf(v, __shfl_xor_sync(0xffffffffu, v, d));
    return v;
}
static __device__ __forceinline__ float warp_sum(float v) {
#pragma unroll
    for (int d = 16; d; d >>= 1) v += __shfl_xor_sync(0xffffffffu, v, d);
    return v;
}

// One scan step: q[j] = sum_i p[i]*T[i][j];  p'[j] = q[j] * exp(obs) (optionally rescaled).
// APPLY: multiply q by 1/max (max computed 1 step earlier), accumulate log(max) into C.
// CMAX : compute block max of new p into wred[] for next step's APPLY.
template <bool APPLY, bool CMAX>
static __device__ __forceinline__ float crf_step(
    const unsigned long long (&tc)[64],
    const float* __restrict__ pin, float* __restrict__ pout,
    float obsv, float& C, float* wred, int warp, int lane, int j)
{
    float eo = __expf(obsv);

    unsigned long long a0 = 0ull, a1 = 0ull, a2 = 0ull, a3 = 0ull;
    const ulonglong2* pv = reinterpret_cast<const ulonglong2*>(pin);
#pragma unroll
    for (int k = 0; k < 32; k += 2) {
        ulonglong2 pa = pv[k];      // p[4k .. 4k+3]   (broadcast LDS.128)
        ulonglong2 pb = pv[k + 1];  // p[4k+4 .. 4k+7]
        asm("fma.rn.f32x2 %0, %1, %2, %0;" : "+l"(a0) : "l"(pa.x), "l"(tc[2 * k + 0]));
        asm("fma.rn.f32x2 %0, %1, %2, %0;" : "+l"(a1) : "l"(pa.y), "l"(tc[2 * k + 1]));
        asm("fma.rn.f32x2 %0, %1, %2, %0;" : "+l"(a2) : "l"(pb.x), "l"(tc[2 * k + 2]));
        asm("fma.rn.f32x2 %0, %1, %2, %0;" : "+l"(a3) : "l"(pb.y), "l"(tc[2 * k + 3]));
    }
    asm("add.rn.f32x2 %0, %0, %1;" : "+l"(a0) : "l"(a2));
    asm("add.rn.f32x2 %0, %0, %1;" : "+l"(a1) : "l"(a3));
    asm("add.rn.f32x2 %0, %0, %1;" : "+l"(a0) : "l"(a1));
    float qx, qy;
    asm("mov.b64 {%0, %1}, %2;" : "=f"(qx), "=f"(qy) : "l"(a0));
    float q = qx + qy;

    if (APPLY) {
        float mx = fmaxf(fmaxf(wred[0], wred[1]), fmaxf(wred[2], wred[3]));
        q = q * __fdividef(1.0f, mx);
        C += __logf(mx);
    }

    float pn = q * eo;
    pout[j] = pn;

    if (CMAX) {
        float m = warp_max(pn);
        if (lane == 0) wred[warp] = m;
    }
    __syncthreads();
    return pn;
}

__global__ void __launch_bounds__(128, 1)
crf_forward_kernel(const float* __restrict__ obs,
                   const float* __restrict__ logA,
                   float* __restrict__ out, int T)
{
    const int b = blockIdx.x;
    const int j = threadIdx.x;
    const int warp = j >> 5;
    const int lane = j & 31;

    __shared__ __align__(16) float psh[2][NSTATES];
    __shared__ float wred[4];

    // Column j of exp(A) in registers, packed as (i even, i odd) f32x2 pairs.
    unsigned long long tc[64];
#pragma unroll
    for (int m = 0; m < 64; ++m) {
        float2 t2;
        t2.x = expf(logA[(2 * m + 0) * NSTATES + j]);
        t2.y = expf(logA[(2 * m + 1) * NSTATES + j]);
        tc[m] = *reinterpret_cast<unsigned long long*>(&t2);
    }

    const float* obj = obs + (size_t)b * ((size_t)T * NSTATES) + j;

    // ---- t = 0: fv0 = obs[:,0,:], p = exp(fv0 - m0), C = m0 ----
    float o0 = obj[0];
    float m0 = warp_max(o0);
    if (lane == 0) wred[warp] = m0;
    __syncthreads();
    m0 = fmaxf(fmaxf(wred[0], wred[1]), fmaxf(wred[2], wred[3]));
    float C = m0;
    psh[0][j] = __expf(o0 - m0);
    __syncthreads();

    // ---- prefetch obs for t = 1..4 ----
    float f0 = obj[1 * NSTATES];
    float f1 = obj[2 * NSTATES];
    float f2 = obj[3 * NSTATES];
    float f3 = obj[4 * NSTATES];

    const int offmax = (T - 1) * NSTATES;
    int off = 5 * NSTATES;  // next element to prefetch (t=5)

    const int G = (T - 1) >> 2;         // full groups of 4 steps (t = 4g+1 .. 4g+4)
    const int rem = (T - 1) & 3;        // leftover steps
    float pn = psh[0][j];

    for (int g = 0; g < G; ++g) {
        float o;
        // slot A: t = 4g+1 (plain)       psh0 -> psh1
        o = f0; f0 = __ldg(obj + (off < offmax ? off : offmax)); off += NSTATES;
        pn = crf_step<false, false>(tc, psh[0], psh[1], o, C, wred, warp, lane, j);
        // slot B: t = 4g+2 (plain)       psh1 -> psh0
        o = f1; f1 = __ldg(obj + (off < offmax ? off : offmax)); off += NSTATES;
        pn = crf_step<false, false>(tc, psh[1], psh[0], o, C, wred, warp, lane, j);
        // slot C: t = 4g+3 (compute max) psh0 -> psh1
        o = f2; f2 = __ldg(obj + (off < offmax ? off : offmax)); off += NSTATES;
        pn = crf_step<false, true >(tc, psh[0], psh[1], o, C, wred, warp, lane, j);
        // slot D: t = 4g+4 (apply scale) psh1 -> psh0
        o = f3; f3 = __ldg(obj + (off < offmax ? off : offmax)); off += NSTATES;
        pn = crf_step<true,  false>(tc, psh[1], psh[0], o, C, wred, warp, lane, j);
    }

    // ---- tail steps (T-1 = 4G + rem); for T=4096: rem = 3 ----
    if (rem > 0) pn = crf_step<false, false>(tc, psh[0], psh[1], f0, C, wred, warp, lane, j);
    if (rem > 1) pn = crf_step<false, false>(tc, psh[1], psh[0], f1, C, wred, warp, lane, j);
    if (rem > 2) pn = crf_step<false, false>(tc, psh[0], psh[1], f2, C, wred, warp, lane, j);

    // ---- final: out[b] = -(C + log(sum_j p[j])) ----
    float s = warp_sum(pn);
    if (lane == 0) wred[warp] = s;
    __syncthreads();
    if (j == 0) {
        float tot = wred[0] + wred[1] + wred[2] + wred[3];
        out[b] = -(C + logf(tot));
    }
}

extern "C" void kernel_launch(void* const* d_in, const int* in_sizes, int n_in,
                              void* d_out, int out_size)
{
    const float* obs  = (const float*)d_in[0];   // [B, T, S] fp32
    const float* logA = (const float*)d_in[1];   // [S, S] fp32
    float* out = (float*)d_out;                  // [B] fp32

    const int B = out_size;                      // 64
    const int T = in_sizes[0] / (B * NSTATES);   // 4096

    crf_forward_kernel<<<B, NSTATES>>>(obs, logA, out, T);
}